// round 15
// baseline (speedup 1.0000x reference)
#include <cuda_runtime.h>
#include <cuda_fp16.h>

namespace {

constexpr int NS      = 512;     // matrix dim (S = K = O = 512)
constexpr int TM      = 16;      // block tile rows
constexpr int TN      = 64;      // block tile cols
constexpr int TK      = 64;      // k chunk (floats); 32 half2 pairs
constexpr int NCHUNK  = NS / TK; // 8
constexpr int THREADS = 128;     // 4 CTAs/SM -> 16 warps/SM
constexpr int KP      = TK / 2;  // 32 k-pairs per chunk
constexpr int ATSTR   = TM + 2;  // As2T row stride (half2) = 18: EVEN -> LDS.64 8B-aligned
                                 // for every kp row; store conflicts <=2-way (loader only)

__global__ __launch_bounds__(THREADS, 4)
void fuzzy_compose_h2_kernel(const float* __restrict__ t, float* __restrict__ out)
{
    // A tile TRANSPOSED: [kpair][m] half2 = (A[m,2kp], A[m,2kp+1]); a-frag = one LDS.64
    __shared__ __half2 As2T[KP][ATSTR];  // 2.3 KB
    // B tile: [kpair][n] half2 = (B[2kp,n], B[2kp+1,n])
    __shared__ __half2 Bs2[KP][TN];      // 8.2 KB

    const int comp = blockIdx.z;             // 0: t0∘t0, 1: t0∘t1
    const int bm   = blockIdx.y * TM;
    const int bn   = blockIdx.x * TN;

    const float* __restrict__ A = t;                     // t0 (left operand of both rules)
    const float* __restrict__ B = t + comp * (NS * NS);  // t[comp] (right operand)

    const int tid = threadIdx.x;
    const int tx  = tid & 15;       // n direction (16)
    const int ty  = tid >> 4;       // m direction (8)
    const int m0  = ty * 2;
    const int n0  = tx * 4;         // half2 columns == float columns

    // ---- loader indices ----
    const int lr = tid >> 4;        // 0..7 (A row base / B k-pair base)
    const int lc = (tid & 15) * 4;  // float column 0..60

    __half2 acc[2][4];
    const __half2 h2zero = __float2half2_rn(0.0f);  // inputs in [0,1): 0 is max-identity
#pragma unroll
    for (int i = 0; i < 2; ++i)
#pragma unroll
        for (int j = 0; j < 4; ++j) acc[i][j] = h2zero;

    // ---- register prefetch of chunk 0 ----
    // A tile 16 rows x 64 cols: rows lr, lr+8
    float4 ra0 = *reinterpret_cast<const float4*>(&A[(bm + lr    ) * NS + lc]);
    float4 ra1 = *reinterpret_cast<const float4*>(&A[(bm + lr + 8) * NS + lc]);
    // B tile 64 k-rows x 64 cols: k-pairs lr, lr+8, lr+16, lr+24 (even/odd rows)
    float4 rb0e = *reinterpret_cast<const float4*>(&B[(2 * (lr     )    ) * NS + bn + lc]);
    float4 rb0o = *reinterpret_cast<const float4*>(&B[(2 * (lr     ) + 1) * NS + bn + lc]);
    float4 rb1e = *reinterpret_cast<const float4*>(&B[(2 * (lr +  8)    ) * NS + bn + lc]);
    float4 rb1o = *reinterpret_cast<const float4*>(&B[(2 * (lr +  8) + 1) * NS + bn + lc]);
    float4 rb2e = *reinterpret_cast<const float4*>(&B[(2 * (lr + 16)    ) * NS + bn + lc]);
    float4 rb2o = *reinterpret_cast<const float4*>(&B[(2 * (lr + 16) + 1) * NS + bn + lc]);
    float4 rb3e = *reinterpret_cast<const float4*>(&B[(2 * (lr + 24)    ) * NS + bn + lc]);
    float4 rb3o = *reinterpret_cast<const float4*>(&B[(2 * (lr + 24) + 1) * NS + bn + lc]);

    for (int c = 0; c < NCHUNK; ++c) {
        __syncthreads();   // previous chunk's compute done (no-op first iter)

        // A (transposed store): float4 covers k..k+3 -> two k-adjacent half2
        // placed in rows lc/2, lc/2+1 at column lr (and lr+8). Scalar 4B stores.
        {
            __half2 h0 = __floats2half2_rn(ra0.x, ra0.y);
            __half2 h1 = __floats2half2_rn(ra0.z, ra0.w);
            As2T[lc / 2    ][lr] = h0;
            As2T[lc / 2 + 1][lr] = h1;
            __half2 g0 = __floats2half2_rn(ra1.x, ra1.y);
            __half2 g1 = __floats2half2_rn(ra1.z, ra1.w);
            As2T[lc / 2    ][lr + 8] = g0;
            As2T[lc / 2 + 1][lr + 8] = g1;
        }
        // B: interleave even/odd k rows into (k,k+1) half2 per n col; STS.128
        {
            uint4 pk;
            __half2 b0 = __floats2half2_rn(rb0e.x, rb0o.x);
            __half2 b1 = __floats2half2_rn(rb0e.y, rb0o.y);
            __half2 b2 = __floats2half2_rn(rb0e.z, rb0o.z);
            __half2 b3 = __floats2half2_rn(rb0e.w, rb0o.w);
            pk.x = *reinterpret_cast<unsigned int*>(&b0);
            pk.y = *reinterpret_cast<unsigned int*>(&b1);
            pk.z = *reinterpret_cast<unsigned int*>(&b2);
            pk.w = *reinterpret_cast<unsigned int*>(&b3);
            *reinterpret_cast<uint4*>(&Bs2[lr][lc]) = pk;

            b0 = __floats2half2_rn(rb1e.x, rb1o.x);
            b1 = __floats2half2_rn(rb1e.y, rb1o.y);
            b2 = __floats2half2_rn(rb1e.z, rb1o.z);
            b3 = __floats2half2_rn(rb1e.w, rb1o.w);
            pk.x = *reinterpret_cast<unsigned int*>(&b0);
            pk.y = *reinterpret_cast<unsigned int*>(&b1);
            pk.z = *reinterpret_cast<unsigned int*>(&b2);
            pk.w = *reinterpret_cast<unsigned int*>(&b3);
            *reinterpret_cast<uint4*>(&Bs2[lr + 8][lc]) = pk;

            b0 = __floats2half2_rn(rb2e.x, rb2o.x);
            b1 = __floats2half2_rn(rb2e.y, rb2o.y);
            b2 = __floats2half2_rn(rb2e.z, rb2o.z);
            b3 = __floats2half2_rn(rb2e.w, rb2o.w);
            pk.x = *reinterpret_cast<unsigned int*>(&b0);
            pk.y = *reinterpret_cast<unsigned int*>(&b1);
            pk.z = *reinterpret_cast<unsigned int*>(&b2);
            pk.w = *reinterpret_cast<unsigned int*>(&b3);
            *reinterpret_cast<uint4*>(&Bs2[lr + 16][lc]) = pk;

            b0 = __floats2half2_rn(rb3e.x, rb3o.x);
            b1 = __floats2half2_rn(rb3e.y, rb3o.y);
            b2 = __floats2half2_rn(rb3e.z, rb3o.z);
            b3 = __floats2half2_rn(rb3e.w, rb3o.w);
            pk.x = *reinterpret_cast<unsigned int*>(&b0);
            pk.y = *reinterpret_cast<unsigned int*>(&b1);
            pk.z = *reinterpret_cast<unsigned int*>(&b2);
            pk.w = *reinterpret_cast<unsigned int*>(&b3);
            *reinterpret_cast<uint4*>(&Bs2[lr + 24][lc]) = pk;
        }
        __syncthreads();   // tiles visible

        if (c + 1 < NCHUNK) {
            const int kn = (c + 1) * TK;
            ra0 = *reinterpret_cast<const float4*>(&A[(bm + lr    ) * NS + kn + lc]);
            ra1 = *reinterpret_cast<const float4*>(&A[(bm + lr + 8) * NS + kn + lc]);
            rb0e = *reinterpret_cast<const float4*>(&B[(kn + 2 * (lr     )    ) * NS + bn + lc]);
            rb0o = *reinterpret_cast<const float4*>(&B[(kn + 2 * (lr     ) + 1) * NS + bn + lc]);
            rb1e = *reinterpret_cast<const float4*>(&B[(kn + 2 * (lr +  8)    ) * NS + bn + lc]);
            rb1o = *reinterpret_cast<const float4*>(&B[(kn + 2 * (lr +  8) + 1) * NS + bn + lc]);
            rb2e = *reinterpret_cast<const float4*>(&B[(kn + 2 * (lr + 16)    ) * NS + bn + lc]);
            rb2o = *reinterpret_cast<const float4*>(&B[(kn + 2 * (lr + 16) + 1) * NS + bn + lc]);
            rb3e = *reinterpret_cast<const float4*>(&B[(kn + 2 * (lr + 24)    ) * NS + bn + lc]);
            rb3o = *reinterpret_cast<const float4*>(&B[(kn + 2 * (lr + 24) + 1) * NS + bn + lc]);
        }

#pragma unroll
        for (int kp = 0; kp < KP; ++kp) {
            // a-fragment: one LDS.64 (rows m0, m0+1 of this kp) — 8B-aligned (ATSTR even)
            const uint2 av = *reinterpret_cast<const uint2*>(&As2T[kp][m0]);
            const __half2 a0 = *reinterpret_cast<const __half2*>(&av.x);
            const __half2 a1 = *reinterpret_cast<const __half2*>(&av.y);

            const uint4 bv = *reinterpret_cast<const uint4*>(&Bs2[kp][n0]);
            const __half2 b0 = *reinterpret_cast<const __half2*>(&bv.x);
            const __half2 b1 = *reinterpret_cast<const __half2*>(&bv.y);
            const __half2 b2 = *reinterpret_cast<const __half2*>(&bv.z);
            const __half2 b3 = *reinterpret_cast<const __half2*>(&bv.w);

            acc[0][0] = __hmax2(acc[0][0], __hmin2(a0, b0));
            acc[0][1] = __hmax2(acc[0][1], __hmin2(a0, b1));
            acc[0][2] = __hmax2(acc[0][2], __hmin2(a0, b2));
            acc[0][3] = __hmax2(acc[0][3], __hmin2(a0, b3));

            acc[1][0] = __hmax2(acc[1][0], __hmin2(a1, b0));
            acc[1][1] = __hmax2(acc[1][1], __hmin2(a1, b1));
            acc[1][2] = __hmax2(acc[1][2], __hmin2(a1, b2));
            acc[1][3] = __hmax2(acc[1][3], __hmin2(a1, b3));
        }
    }

    // ---- epilogue: fold k-pair lanes, then out = t + num*(1 - t), t = t[comp] ----
    float* __restrict__ O = out + comp * (NS * NS);
#pragma unroll
    for (int i = 0; i < 2; ++i) {
        const int row = bm + m0 + i;
        const float4 tv = *reinterpret_cast<const float4*>(&B[row * NS + bn + n0]);
        float4 r;
        const float n00 = fmaxf(__low2float(acc[i][0]), __high2float(acc[i][0]));
        const float n01 = fmaxf(__low2float(acc[i][1]), __high2float(acc[i][1]));
        const float n02 = fmaxf(__low2float(acc[i][2]), __high2float(acc[i][2]));
        const float n03 = fmaxf(__low2float(acc[i][3]), __high2float(acc[i][3]));
        r.x = tv.x + n00 * (1.0f - tv.x);
        r.y = tv.y + n01 * (1.0f - tv.y);
        r.z = tv.z + n02 * (1.0f - tv.z);
        r.w = tv.w + n03 * (1.0f - tv.w);
        *reinterpret_cast<float4*>(&O[row * NS + bn + n0]) = r;
    }
}

} // namespace

extern "C" void kernel_launch(void* const* d_in, const int* in_sizes, int n_in,
                              void* d_out, int out_size)
{
    (void)in_sizes; (void)n_in; (void)out_size;
    const float* t = reinterpret_cast<const float*>(d_in[0]);
    float* out     = reinterpret_cast<float*>(d_out);

    dim3 grid(NS / TN, NS / TM, 2);   // 8 x 32 x 2 = 512 blocks, 4 CTAs/SM
    fuzzy_compose_h2_kernel<<<grid, THREADS>>>(t, out);
}

// round 16
// speedup vs baseline: 1.0144x; 1.0144x over previous
#include <cuda_runtime.h>
#include <cuda_fp16.h>

namespace {

constexpr int NS      = 512;     // matrix dim (S = K = O = 512)
constexpr int TM      = 16;      // block tile rows
constexpr int TN      = 64;      // block tile cols
constexpr int TK      = 64;      // k chunk (floats); 32 half2 pairs
constexpr int KSPLIT  = 2;       // k-range split across blockIdx.z
constexpr int KHALF   = NS / KSPLIT;      // 256
constexpr int NCHUNK  = KHALF / TK;       // 4 chunks per block
constexpr int THREADS = 128;     // 4 CTAs/SM
constexpr int KP      = TK / 2;  // 32 k-pairs per chunk
constexpr int ASTR    = KP + 2;  // As2 row stride (half2) = 34: EVEN (STS.64 8B-aligned)

// Partial num scratch: [comp*2 + ks][s][o], each element written exactly once.
__device__ float g_num[2 * KSPLIT * NS * NS];   // 4 MB

__global__ __launch_bounds__(THREADS, 4)
void fuzzy_compose_h2_main(const float* __restrict__ t)
{
    __shared__ __half2 As2[TM][ASTR];   // 2.2 KB
    __shared__ __half2 Bs2[KP][TN];     // 8.2 KB

    const int bz   = blockIdx.z;      // 0..3
    const int comp = bz >> 1;         // 0: t0∘t0, 1: t0∘t1
    const int ks   = bz & 1;          // k half
    const int kb   = ks * KHALF;      // k base offset
    const int bm   = blockIdx.y * TM;
    const int bn   = blockIdx.x * TN;

    const float* __restrict__ A = t;                     // t0
    const float* __restrict__ B = t + comp * (NS * NS);  // t[comp]

    const int tid = threadIdx.x;
    const int tx  = tid & 15;
    const int ty  = tid >> 4;
    const int m0  = ty * 2;
    const int n0  = tx * 4;

    const int lr = tid >> 4;        // 0..7
    const int lc = (tid & 15) * 4;  // 0..60 (lc/2 even -> STS.64 aligned)

    __half2 acc[2][4];
    const __half2 h2zero = __float2half2_rn(0.0f);
#pragma unroll
    for (int i = 0; i < 2; ++i)
#pragma unroll
        for (int j = 0; j < 4; ++j) acc[i][j] = h2zero;

    // ---- register prefetch of chunk 0 ----
    float4 ra0 = *reinterpret_cast<const float4*>(&A[(bm + lr    ) * NS + kb + lc]);
    float4 ra1 = *reinterpret_cast<const float4*>(&A[(bm + lr + 8) * NS + kb + lc]);
    float4 rb0e = *reinterpret_cast<const float4*>(&B[(kb + 2 * (lr     )    ) * NS + bn + lc]);
    float4 rb0o = *reinterpret_cast<const float4*>(&B[(kb + 2 * (lr     ) + 1) * NS + bn + lc]);
    float4 rb1e = *reinterpret_cast<const float4*>(&B[(kb + 2 * (lr +  8)    ) * NS + bn + lc]);
    float4 rb1o = *reinterpret_cast<const float4*>(&B[(kb + 2 * (lr +  8) + 1) * NS + bn + lc]);
    float4 rb2e = *reinterpret_cast<const float4*>(&B[(kb + 2 * (lr + 16)    ) * NS + bn + lc]);
    float4 rb2o = *reinterpret_cast<const float4*>(&B[(kb + 2 * (lr + 16) + 1) * NS + bn + lc]);
    float4 rb3e = *reinterpret_cast<const float4*>(&B[(kb + 2 * (lr + 24)    ) * NS + bn + lc]);
    float4 rb3o = *reinterpret_cast<const float4*>(&B[(kb + 2 * (lr + 24) + 1) * NS + bn + lc]);

    for (int c = 0; c < NCHUNK; ++c) {
        __syncthreads();

        // A: float4 covers k..k+3 -> two k-adjacent half2; STS.64 per row
        {
            __half2 h0 = __floats2half2_rn(ra0.x, ra0.y);
            __half2 h1 = __floats2half2_rn(ra0.z, ra0.w);
            uint2 p; p.x = *reinterpret_cast<unsigned int*>(&h0);
                     p.y = *reinterpret_cast<unsigned int*>(&h1);
            *reinterpret_cast<uint2*>(&As2[lr][lc / 2]) = p;

            h0 = __floats2half2_rn(ra1.x, ra1.y);
            h1 = __floats2half2_rn(ra1.z, ra1.w);
            p.x = *reinterpret_cast<unsigned int*>(&h0);
            p.y = *reinterpret_cast<unsigned int*>(&h1);
            *reinterpret_cast<uint2*>(&As2[lr + 8][lc / 2]) = p;
        }
        // B: interleave even/odd k rows into (k,k+1) half2 per n col; STS.128
        {
            uint4 pk;
            __half2 b0 = __floats2half2_rn(rb0e.x, rb0o.x);
            __half2 b1 = __floats2half2_rn(rb0e.y, rb0o.y);
            __half2 b2 = __floats2half2_rn(rb0e.z, rb0o.z);
            __half2 b3 = __floats2half2_rn(rb0e.w, rb0o.w);
            pk.x = *reinterpret_cast<unsigned int*>(&b0);
            pk.y = *reinterpret_cast<unsigned int*>(&b1);
            pk.z = *reinterpret_cast<unsigned int*>(&b2);
            pk.w = *reinterpret_cast<unsigned int*>(&b3);
            *reinterpret_cast<uint4*>(&Bs2[lr][lc]) = pk;

            b0 = __floats2half2_rn(rb1e.x, rb1o.x);
            b1 = __floats2half2_rn(rb1e.y, rb1o.y);
            b2 = __floats2half2_rn(rb1e.z, rb1o.z);
            b3 = __floats2half2_rn(rb1e.w, rb1o.w);
            pk.x = *reinterpret_cast<unsigned int*>(&b0);
            pk.y = *reinterpret_cast<unsigned int*>(&b1);
            pk.z = *reinterpret_cast<unsigned int*>(&b2);
            pk.w = *reinterpret_cast<unsigned int*>(&b3);
            *reinterpret_cast<uint4*>(&Bs2[lr + 8][lc]) = pk;

            b0 = __floats2half2_rn(rb2e.x, rb2o.x);
            b1 = __floats2half2_rn(rb2e.y, rb2o.y);
            b2 = __floats2half2_rn(rb2e.z, rb2o.z);
            b3 = __floats2half2_rn(rb2e.w, rb2o.w);
            pk.x = *reinterpret_cast<unsigned int*>(&b0);
            pk.y = *reinterpret_cast<unsigned int*>(&b1);
            pk.z = *reinterpret_cast<unsigned int*>(&b2);
            pk.w = *reinterpret_cast<unsigned int*>(&b3);
            *reinterpret_cast<uint4*>(&Bs2[lr + 16][lc]) = pk;

            b0 = __floats2half2_rn(rb3e.x, rb3o.x);
            b1 = __floats2half2_rn(rb3e.y, rb3o.y);
            b2 = __floats2half2_rn(rb3e.z, rb3o.z);
            b3 = __floats2half2_rn(rb3e.w, rb3o.w);
            pk.x = *reinterpret_cast<unsigned int*>(&b0);
            pk.y = *reinterpret_cast<unsigned int*>(&b1);
            pk.z = *reinterpret_cast<unsigned int*>(&b2);
            pk.w = *reinterpret_cast<unsigned int*>(&b3);
            *reinterpret_cast<uint4*>(&Bs2[lr + 24][lc]) = pk;
        }
        __syncthreads();

        if (c + 1 < NCHUNK) {
            const int kn = kb + (c + 1) * TK;
            ra0 = *reinterpret_cast<const float4*>(&A[(bm + lr    ) * NS + kn + lc]);
            ra1 = *reinterpret_cast<const float4*>(&A[(bm + lr + 8) * NS + kn + lc]);
            rb0e = *reinterpret_cast<const float4*>(&B[(kn + 2 * (lr     )    ) * NS + bn + lc]);
            rb0o = *reinterpret_cast<const float4*>(&B[(kn + 2 * (lr     ) + 1) * NS + bn + lc]);
            rb1e = *reinterpret_cast<const float4*>(&B[(kn + 2 * (lr +  8)    ) * NS + bn + lc]);
            rb1o = *reinterpret_cast<const float4*>(&B[(kn + 2 * (lr +  8) + 1) * NS + bn + lc]);
            rb2e = *reinterpret_cast<const float4*>(&B[(kn + 2 * (lr + 16)    ) * NS + bn + lc]);
            rb2o = *reinterpret_cast<const float4*>(&B[(kn + 2 * (lr + 16) + 1) * NS + bn + lc]);
            rb3e = *reinterpret_cast<const float4*>(&B[(kn + 2 * (lr + 24)    ) * NS + bn + lc]);
            rb3o = *reinterpret_cast<const float4*>(&B[(kn + 2 * (lr + 24) + 1) * NS + bn + lc]);
        }

#pragma unroll
        for (int kp = 0; kp < KP; ++kp) {
            const __half2 a0 = As2[m0 + 0][kp];
            const __half2 a1 = As2[m0 + 1][kp];

            const uint4 bv = *reinterpret_cast<const uint4*>(&Bs2[kp][n0]);
            const __half2 b0 = *reinterpret_cast<const __half2*>(&bv.x);
            const __half2 b1 = *reinterpret_cast<const __half2*>(&bv.y);
            const __half2 b2 = *reinterpret_cast<const __half2*>(&bv.z);
            const __half2 b3 = *reinterpret_cast<const __half2*>(&bv.w);

            acc[0][0] = __hmax2(acc[0][0], __hmin2(a0, b0));
            acc[0][1] = __hmax2(acc[0][1], __hmin2(a0, b1));
            acc[0][2] = __hmax2(acc[0][2], __hmin2(a0, b2));
            acc[0][3] = __hmax2(acc[0][3], __hmin2(a0, b3));

            acc[1][0] = __hmax2(acc[1][0], __hmin2(a1, b0));
            acc[1][1] = __hmax2(acc[1][1], __hmin2(a1, b1));
            acc[1][2] = __hmax2(acc[1][2], __hmin2(a1, b2));
            acc[1][3] = __hmax2(acc[1][3], __hmin2(a1, b3));
        }
    }

    // ---- epilogue: fold k-pair lanes, store partial num to scratch ----
    float* __restrict__ Np = g_num + bz * (NS * NS);
#pragma unroll
    for (int i = 0; i < 2; ++i) {
        const int row = bm + m0 + i;
        float4 r;
        r.x = fmaxf(__low2float(acc[i][0]), __high2float(acc[i][0]));
        r.y = fmaxf(__low2float(acc[i][1]), __high2float(acc[i][1]));
        r.z = fmaxf(__low2float(acc[i][2]), __high2float(acc[i][2]));
        r.w = fmaxf(__low2float(acc[i][3]), __high2float(acc[i][3]));
        *reinterpret_cast<float4*>(&Np[row * NS + bn + n0]) = r;
    }
}

// Combine: nm = max(num_ks0, num_ks1); out = t + nm - t*nm. 2*NS*NS/4 float4 elems.
constexpr int CTHREADS = 512;
constexpr int Q4       = NS * NS / 4;   // 65536 float4 per matrix

__global__ __launch_bounds__(CTHREADS)
void fuzzy_compose_combine(const float* __restrict__ t, float* __restrict__ out)
{
    const int i4 = blockIdx.x * CTHREADS + threadIdx.x;   // 0 .. 2*Q4-1
    const int comp = i4 >> 16;          // i4 / Q4
    const int r    = i4 & (Q4 - 1);     // i4 % Q4

    const float4* __restrict__ nf = reinterpret_cast<const float4*>(g_num);
    const float4 na = nf[(comp * 2 + 0) * Q4 + r];
    const float4 nb = nf[(comp * 2 + 1) * Q4 + r];
    const float4 tv = reinterpret_cast<const float4*>(t)[i4];

    float4 o;
    float nm;
    nm = fmaxf(na.x, nb.x); o.x = tv.x + nm * (1.0f - tv.x);
    nm = fmaxf(na.y, nb.y); o.y = tv.y + nm * (1.0f - tv.y);
    nm = fmaxf(na.z, nb.z); o.z = tv.z + nm * (1.0f - tv.z);
    nm = fmaxf(na.w, nb.w); o.w = tv.w + nm * (1.0f - tv.w);
    reinterpret_cast<float4*>(out)[i4] = o;
}

} // namespace

extern "C" void kernel_launch(void* const* d_in, const int* in_sizes, int n_in,
                              void* d_out, int out_size)
{
    (void)in_sizes; (void)n_in; (void)out_size;
    const float* t = reinterpret_cast<const float*>(d_in[0]);
    float* out     = reinterpret_cast<float*>(d_out);

    dim3 grid(NS / TN, NS / TM, 2 * KSPLIT);   // 8 x 32 x 4 = 1024 blocks
    fuzzy_compose_h2_main<<<grid, THREADS>>>(t);

    const int total4 = 2 * Q4;                  // 131072 float4
    fuzzy_compose_combine<<<total4 / CTHREADS, CTHREADS>>>(t, out);
}

// round 17
// speedup vs baseline: 1.0762x; 1.0610x over previous
#include <cuda_runtime.h>
#include <cuda_fp16.h>

namespace {

constexpr int NS      = 512;     // matrix dim (S = K = O = 512)
constexpr int TM      = 16;      // block tile rows
constexpr int TN      = 64;      // block tile cols
constexpr int TK      = 64;      // k chunk (floats); 32 half2 pairs
constexpr int KSPLIT  = 2;       // k-range split across blockIdx.z
constexpr int KHALF   = NS / KSPLIT;      // 256
constexpr int NCHUNK  = KHALF / TK;       // 4 chunks per block
constexpr int THREADS = 128;     // 4 CTAs/SM
constexpr int KP      = TK / 2;  // 32 k-pairs per chunk
constexpr int ASTR    = KP + 2;  // As2 row stride (half2) = 34: EVEN (STS.64 8B-aligned)

// Partial num scratch in fp16 (EXACT: each partial is a max of fp16 values).
// Layout: [comp*2 + ks][s][o], each element written exactly once. 2 MB.
__device__ __half g_num[2 * KSPLIT * NS * NS];

__global__ __launch_bounds__(THREADS, 4)
void fuzzy_compose_h2_main(const float* __restrict__ t)
{
    __shared__ __half2 As2[TM][ASTR];   // 2.2 KB
    __shared__ __half2 Bs2[KP][TN];     // 8.2 KB

    const int bz   = blockIdx.z;      // 0..3
    const int comp = bz >> 1;         // 0: t0∘t0, 1: t0∘t1
    const int ks   = bz & 1;          // k half
    const int kb   = ks * KHALF;      // k base offset
    const int bm   = blockIdx.y * TM;
    const int bn   = blockIdx.x * TN;

    const float* __restrict__ A = t;                     // t0
    const float* __restrict__ B = t + comp * (NS * NS);  // t[comp]

    const int tid = threadIdx.x;
    const int tx  = tid & 15;
    const int ty  = tid >> 4;
    const int m0  = ty * 2;
    const int n0  = tx * 4;

    const int lr = tid >> 4;        // 0..7
    const int lc = (tid & 15) * 4;  // 0..60 (lc/2 even -> STS.64 aligned)

    __half2 acc[2][4];
    const __half2 h2zero = __float2half2_rn(0.0f);
#pragma unroll
    for (int i = 0; i < 2; ++i)
#pragma unroll
        for (int j = 0; j < 4; ++j) acc[i][j] = h2zero;

    // ---- register prefetch of chunk 0 ----
    float4 ra0 = *reinterpret_cast<const float4*>(&A[(bm + lr    ) * NS + kb + lc]);
    float4 ra1 = *reinterpret_cast<const float4*>(&A[(bm + lr + 8) * NS + kb + lc]);
    float4 rb0e = *reinterpret_cast<const float4*>(&B[(kb + 2 * (lr     )    ) * NS + bn + lc]);
    float4 rb0o = *reinterpret_cast<const float4*>(&B[(kb + 2 * (lr     ) + 1) * NS + bn + lc]);
    float4 rb1e = *reinterpret_cast<const float4*>(&B[(kb + 2 * (lr +  8)    ) * NS + bn + lc]);
    float4 rb1o = *reinterpret_cast<const float4*>(&B[(kb + 2 * (lr +  8) + 1) * NS + bn + lc]);
    float4 rb2e = *reinterpret_cast<const float4*>(&B[(kb + 2 * (lr + 16)    ) * NS + bn + lc]);
    float4 rb2o = *reinterpret_cast<const float4*>(&B[(kb + 2 * (lr + 16) + 1) * NS + bn + lc]);
    float4 rb3e = *reinterpret_cast<const float4*>(&B[(kb + 2 * (lr + 24)    ) * NS + bn + lc]);
    float4 rb3o = *reinterpret_cast<const float4*>(&B[(kb + 2 * (lr + 24) + 1) * NS + bn + lc]);

    for (int c = 0; c < NCHUNK; ++c) {
        __syncthreads();

        // A: float4 covers k..k+3 -> two k-adjacent half2; STS.64 per row
        {
            __half2 h0 = __floats2half2_rn(ra0.x, ra0.y);
            __half2 h1 = __floats2half2_rn(ra0.z, ra0.w);
            uint2 p; p.x = *reinterpret_cast<unsigned int*>(&h0);
                     p.y = *reinterpret_cast<unsigned int*>(&h1);
            *reinterpret_cast<uint2*>(&As2[lr][lc / 2]) = p;

            h0 = __floats2half2_rn(ra1.x, ra1.y);
            h1 = __floats2half2_rn(ra1.z, ra1.w);
            p.x = *reinterpret_cast<unsigned int*>(&h0);
            p.y = *reinterpret_cast<unsigned int*>(&h1);
            *reinterpret_cast<uint2*>(&As2[lr + 8][lc / 2]) = p;
        }
        // B: interleave even/odd k rows into (k,k+1) half2 per n col; STS.128
        {
            uint4 pk;
            __half2 b0 = __floats2half2_rn(rb0e.x, rb0o.x);
            __half2 b1 = __floats2half2_rn(rb0e.y, rb0o.y);
            __half2 b2 = __floats2half2_rn(rb0e.z, rb0o.z);
            __half2 b3 = __floats2half2_rn(rb0e.w, rb0o.w);
            pk.x = *reinterpret_cast<unsigned int*>(&b0);
            pk.y = *reinterpret_cast<unsigned int*>(&b1);
            pk.z = *reinterpret_cast<unsigned int*>(&b2);
            pk.w = *reinterpret_cast<unsigned int*>(&b3);
            *reinterpret_cast<uint4*>(&Bs2[lr][lc]) = pk;

            b0 = __floats2half2_rn(rb1e.x, rb1o.x);
            b1 = __floats2half2_rn(rb1e.y, rb1o.y);
            b2 = __floats2half2_rn(rb1e.z, rb1o.z);
            b3 = __floats2half2_rn(rb1e.w, rb1o.w);
            pk.x = *reinterpret_cast<unsigned int*>(&b0);
            pk.y = *reinterpret_cast<unsigned int*>(&b1);
            pk.z = *reinterpret_cast<unsigned int*>(&b2);
            pk.w = *reinterpret_cast<unsigned int*>(&b3);
            *reinterpret_cast<uint4*>(&Bs2[lr + 8][lc]) = pk;

            b0 = __floats2half2_rn(rb2e.x, rb2o.x);
            b1 = __floats2half2_rn(rb2e.y, rb2o.y);
            b2 = __floats2half2_rn(rb2e.z, rb2o.z);
            b3 = __floats2half2_rn(rb2e.w, rb2o.w);
            pk.x = *reinterpret_cast<unsigned int*>(&b0);
            pk.y = *reinterpret_cast<unsigned int*>(&b1);
            pk.z = *reinterpret_cast<unsigned int*>(&b2);
            pk.w = *reinterpret_cast<unsigned int*>(&b3);
            *reinterpret_cast<uint4*>(&Bs2[lr + 16][lc]) = pk;

            b0 = __floats2half2_rn(rb3e.x, rb3o.x);
            b1 = __floats2half2_rn(rb3e.y, rb3o.y);
            b2 = __floats2half2_rn(rb3e.z, rb3o.z);
            b3 = __floats2half2_rn(rb3e.w, rb3o.w);
            pk.x = *reinterpret_cast<unsigned int*>(&b0);
            pk.y = *reinterpret_cast<unsigned int*>(&b1);
            pk.z = *reinterpret_cast<unsigned int*>(&b2);
            pk.w = *reinterpret_cast<unsigned int*>(&b3);
            *reinterpret_cast<uint4*>(&Bs2[lr + 24][lc]) = pk;
        }
        __syncthreads();

        if (c + 1 < NCHUNK) {
            const int kn = kb + (c + 1) * TK;
            ra0 = *reinterpret_cast<const float4*>(&A[(bm + lr    ) * NS + kn + lc]);
            ra1 = *reinterpret_cast<const float4*>(&A[(bm + lr + 8) * NS + kn + lc]);
            rb0e = *reinterpret_cast<const float4*>(&B[(kn + 2 * (lr     )    ) * NS + bn + lc]);
            rb0o = *reinterpret_cast<const float4*>(&B[(kn + 2 * (lr     ) + 1) * NS + bn + lc]);
            rb1e = *reinterpret_cast<const float4*>(&B[(kn + 2 * (lr +  8)    ) * NS + bn + lc]);
            rb1o = *reinterpret_cast<const float4*>(&B[(kn + 2 * (lr +  8) + 1) * NS + bn + lc]);
            rb2e = *reinterpret_cast<const float4*>(&B[(kn + 2 * (lr + 16)    ) * NS + bn + lc]);
            rb2o = *reinterpret_cast<const float4*>(&B[(kn + 2 * (lr + 16) + 1) * NS + bn + lc]);
            rb3e = *reinterpret_cast<const float4*>(&B[(kn + 2 * (lr + 24)    ) * NS + bn + lc]);
            rb3o = *reinterpret_cast<const float4*>(&B[(kn + 2 * (lr + 24) + 1) * NS + bn + lc]);
        }

#pragma unroll
        for (int kp = 0; kp < KP; ++kp) {
            const __half2 a0 = As2[m0 + 0][kp];
            const __half2 a1 = As2[m0 + 1][kp];

            const uint4 bv = *reinterpret_cast<const uint4*>(&Bs2[kp][n0]);
            const __half2 b0 = *reinterpret_cast<const __half2*>(&bv.x);
            const __half2 b1 = *reinterpret_cast<const __half2*>(&bv.y);
            const __half2 b2 = *reinterpret_cast<const __half2*>(&bv.z);
            const __half2 b3 = *reinterpret_cast<const __half2*>(&bv.w);

            acc[0][0] = __hmax2(acc[0][0], __hmin2(a0, b0));
            acc[0][1] = __hmax2(acc[0][1], __hmin2(a0, b1));
            acc[0][2] = __hmax2(acc[0][2], __hmin2(a0, b2));
            acc[0][3] = __hmax2(acc[0][3], __hmin2(a0, b3));

            acc[1][0] = __hmax2(acc[1][0], __hmin2(a1, b0));
            acc[1][1] = __hmax2(acc[1][1], __hmin2(a1, b1));
            acc[1][2] = __hmax2(acc[1][2], __hmin2(a1, b2));
            acc[1][3] = __hmax2(acc[1][3], __hmin2(a1, b3));
        }
    }

    // ---- epilogue: fold k-pair lanes (exact fp16 max), store half4 per row ----
    __half* __restrict__ Np = g_num + bz * (NS * NS);
#pragma unroll
    for (int i = 0; i < 2; ++i) {
        const int row = bm + m0 + i;
        // n00..n03 as packed half2 pairs: (n00,n01), (n02,n03)
        __half2 p01, p23;
        p01 = __halves2half2(__hmax(__low2half(acc[i][0]), __high2half(acc[i][0])),
                             __hmax(__low2half(acc[i][1]), __high2half(acc[i][1])));
        p23 = __halves2half2(__hmax(__low2half(acc[i][2]), __high2half(acc[i][2])),
                             __hmax(__low2half(acc[i][3]), __high2half(acc[i][3])));
        uint2 pk;
        pk.x = *reinterpret_cast<unsigned int*>(&p01);
        pk.y = *reinterpret_cast<unsigned int*>(&p23);
        // offset in halfs: row*NS + bn + n0 (n0 multiple of 4 -> 8B aligned)
        *reinterpret_cast<uint2*>(&Np[row * NS + bn + n0]) = pk;
    }
}

// Combine: nm = max(num_ks0, num_ks1) (exact fp16 max), out = t + nm - t*nm (fp32).
// 2 output-float4 per thread, all loads independent (MLP 6).
constexpr int CTHREADS = 256;
constexpr int Q4       = NS * NS / 4;   // 65536 float4 per matrix

__global__ __launch_bounds__(CTHREADS)
void fuzzy_compose_combine(const float* __restrict__ t, float* __restrict__ out)
{
    const int g = blockIdx.x * CTHREADS + threadIdx.x;   // 0 .. Q4-1 (per comp)
    const uint2* __restrict__ nh = reinterpret_cast<const uint2*>(g_num);
    const float4* __restrict__ tf = reinterpret_cast<const float4*>(t);
    float4* __restrict__ of = reinterpret_cast<float4*>(out);

    // Issue all loads up front (independent), then compute.
    const uint2  na0 = nh[0 * Q4 + g];            // comp0, ks0
    const uint2  nb0 = nh[1 * Q4 + g];            // comp0, ks1
    const uint2  na1 = nh[2 * Q4 + g];            // comp1, ks0
    const uint2  nb1 = nh[3 * Q4 + g];            // comp1, ks1
    const float4 tv0 = tf[g];
    const float4 tv1 = tf[Q4 + g];

#pragma unroll
    for (int u = 0; u < 2; ++u) {
        const uint2 na = u ? na1 : na0;
        const uint2 nb = u ? nb1 : nb0;
        const float4 tv = u ? tv1 : tv0;

        const __half2 alo = *reinterpret_cast<const __half2*>(&na.x);
        const __half2 ahi = *reinterpret_cast<const __half2*>(&na.y);
        const __half2 blo = *reinterpret_cast<const __half2*>(&nb.x);
        const __half2 bhi = *reinterpret_cast<const __half2*>(&nb.y);

        const __half2 mlo = __hmax2(alo, blo);
        const __half2 mhi = __hmax2(ahi, bhi);
        const float2 f01 = __half22float2(mlo);
        const float2 f23 = __half22float2(mhi);

        float4 o;
        o.x = tv.x + f01.x * (1.0f - tv.x);
        o.y = tv.y + f01.y * (1.0f - tv.y);
        o.z = tv.z + f23.x * (1.0f - tv.z);
        o.w = tv.w + f23.y * (1.0f - tv.w);
        of[u * Q4 + g] = o;
    }
}

} // namespace

extern "C" void kernel_launch(void* const* d_in, const int* in_sizes, int n_in,
                              void* d_out, int out_size)
{
    (void)in_sizes; (void)n_in; (void)out_size;
    const float* t = reinterpret_cast<const float*>(d_in[0]);
    float* out     = reinterpret_cast<float*>(d_out);

    dim3 grid(NS / TN, NS / TM, 2 * KSPLIT);   // 8 x 32 x 4 = 1024 blocks
    fuzzy_compose_h2_main<<<grid, THREADS>>>(t);

    fuzzy_compose_combine<<<Q4 / CTHREADS, CTHREADS>>>(t, out);   // 256 blocks x 256 thr
}